// round 7
// baseline (speedup 1.0000x reference)
#include <cuda_runtime.h>
#include <cuda_bf16.h>

// Problem constants (fixed-shape dataset)
#define D 128
#define H 256
#define MAXN 40000
#define MAXE 640000
#define LN_EPS 1e-5f

// Scratch: edge-message aggregation (scatter target) + per-receiver counts.
__device__ float g_agg[MAXN * D];
__device__ float g_cnt[MAXN];
// Index dtype flag: 1 if edge_index is int64, 0 if int32 (JAX default x64-off -> int32).
__device__ int g_idx64;

__device__ __forceinline__ float silu_f(float x) {
    return x / (1.0f + __expf(-x));
}

// Detect index dtype: for int64 data with values in [0, 2^31), every odd
// int32 word is a zero high-word. For int32 data these are real node ids.
__global__ void probe_kernel(const int* __restrict__ e32) {
    if (blockIdx.x == 0 && threadIdx.x == 0) {
        int all0 = 1;
#pragma unroll 1
        for (int i = 0; i < 64; ++i) {
            if (e32[2 * i + 1] != 0) { all0 = 0; break; }
        }
        g_idx64 = all0;
    }
}

__global__ void zero_kernel(int N) {
    int i = blockIdx.x * blockDim.x + threadIdx.x;
    int na = N * D;
    if (i < na) g_agg[i] = 0.0f;
    if (i < N)  g_cnt[i] = 0.0f;
}

// Fused MLP+LN kernel.
// MODE 0: edge   (A = [sender_x[src] | receiver_x[dst] | edge_attr], KTOT=384)
//         epilogue: edge_out = edge_attr + y ; scatter y into g_agg[dst], count++
// MODE 1: node   (A = [receiver_x | g_agg/max(cnt,1)], KTOT=256)
//         epilogue: receiver_out = receiver_x + y
// MODE 2: sender (A = sender_x, KTOT=128)
//         epilogue: sender_out = sender_x + y
//
// Block: 256 threads, 32 rows. GEMM1 -> SiLU (smem) -> GEMM2 -> warp LN.
// GEMM1: rg=tid>>5 owns rows rg*4..+3, lane owns cols lane*8..+7 (4x8 microtile).
// GEMM2: rg rows rg*4..+3, lane cols lane*4..+3 (4x4 microtile)
//   => each output row's 128 cols live in a single warp -> LN via shuffles.
#define AS_STRIDE 36
#define HS_STRIDE 264
#define SMEM_FLOATS (32 * AS_STRIDE + 32 * H + 32 * HS_STRIDE)

template <int KTOT, int MODE>
__global__ void __launch_bounds__(256, 2) mlp_kernel(
    const float* __restrict__ sx,
    const float* __restrict__ rx,
    const float* __restrict__ ea,
    const int* e32,               // edge_index viewed as int32 (aliases e64)
    const long long* e64,         // edge_index viewed as int64 (same ptr)
    const float* __restrict__ w1, const float* __restrict__ b1,
    const float* __restrict__ w2, const float* __restrict__ b2,
    const float* __restrict__ gm, const float* __restrict__ bt,
    float* __restrict__ out,
    int M, int E)
{
    extern __shared__ float smem[];
    float* As = smem;                       // [32][AS_STRIDE]
    float* Bs = smem + 32 * AS_STRIDE;      // [32][256] (GEMM1) / [32][128] (GEMM2)
    float* Hs = Bs + 32 * H;                // [32][HS_STRIDE]

    const int tid  = threadIdx.x;
    const int lane = tid & 31;
    const int rg   = tid >> 5;
    const int row0 = blockIdx.x * 32;
    const int is64 = (MODE == 0) ? g_idx64 : 0;

    float acc1[4][8];
#pragma unroll
    for (int i = 0; i < 4; i++)
#pragma unroll
        for (int j = 0; j < 8; j++) acc1[i][j] = 0.0f;

    const float4* Bs4 = (const float4*)Bs;

    // ---------------- GEMM1: C1[32,H] = A[32,KTOT] @ w1[KTOT,H] ----------------
    for (int kt = 0; kt < KTOT / 32; ++kt) {
        // Load A tile (1 float4 per thread): r=tid>>3, k_local=(tid&7)*4
        {
            int r  = tid >> 3;
            int kl = (tid & 7) * 4;
            int kg = kt * 32 + kl;
            int row = row0 + r;              // GLOBAL row
            float4 v = make_float4(0.f, 0.f, 0.f, 0.f);
            if (row < M) {
                if (MODE == 0) {
                    const float* p;
                    if (kg < 128) {
                        long long s = is64 ? e64[row] : (long long)e32[row];
                        p = sx + (size_t)s * D + kg;
                    } else if (kg < 256) {
                        long long d = is64 ? e64[E + row] : (long long)e32[E + row];
                        p = rx + (size_t)d * D + (kg - 128);
                    } else {
                        p = ea + (size_t)row * D + (kg - 256);
                    }
                    v = *(const float4*)p;
                } else if (MODE == 1) {
                    if (kg < 128) {
                        v = *(const float4*)(rx + (size_t)row * D + kg);
                    } else {
                        float rc = 1.0f / fmaxf(g_cnt[row], 1.0f);
                        float4 t = *(const float4*)(g_agg + (size_t)row * D + (kg - 128));
                        v.x = t.x * rc; v.y = t.y * rc; v.z = t.z * rc; v.w = t.w * rc;
                    }
                } else {
                    v = *(const float4*)(sx + (size_t)row * D + kg);
                }
            }
            *(float4*)(As + r * AS_STRIDE + kl) = v;
        }
        // Load B tile [32][256]: 8 float4 per thread
#pragma unroll
        for (int j = 0; j < 8; j++) {
            int idx = tid + j * 256;
            int k  = idx >> 6;
            int n4 = idx & 63;
            ((float4*)Bs)[k * 64 + n4] =
                ((const float4*)(w1 + (size_t)(kt * 32 + k) * H))[n4];
        }
        __syncthreads();

#pragma unroll
        for (int kk = 0; kk < 32; ++kk) {
            float a0 = As[(rg * 4 + 0) * AS_STRIDE + kk];
            float a1 = As[(rg * 4 + 1) * AS_STRIDE + kk];
            float a2 = As[(rg * 4 + 2) * AS_STRIDE + kk];
            float a3 = As[(rg * 4 + 3) * AS_STRIDE + kk];
            float4 bA = Bs4[kk * 64 + lane * 2];
            float4 bB = Bs4[kk * 64 + lane * 2 + 1];
            acc1[0][0] += a0 * bA.x; acc1[0][1] += a0 * bA.y; acc1[0][2] += a0 * bA.z; acc1[0][3] += a0 * bA.w;
            acc1[0][4] += a0 * bB.x; acc1[0][5] += a0 * bB.y; acc1[0][6] += a0 * bB.z; acc1[0][7] += a0 * bB.w;
            acc1[1][0] += a1 * bA.x; acc1[1][1] += a1 * bA.y; acc1[1][2] += a1 * bA.z; acc1[1][3] += a1 * bA.w;
            acc1[1][4] += a1 * bB.x; acc1[1][5] += a1 * bB.y; acc1[1][6] += a1 * bB.z; acc1[1][7] += a1 * bB.w;
            acc1[2][0] += a2 * bA.x; acc1[2][1] += a2 * bA.y; acc1[2][2] += a2 * bA.z; acc1[2][3] += a2 * bA.w;
            acc1[2][4] += a2 * bB.x; acc1[2][5] += a2 * bB.y; acc1[2][6] += a2 * bB.z; acc1[2][7] += a2 * bB.w;
            acc1[3][0] += a3 * bA.x; acc1[3][1] += a3 * bA.y; acc1[3][2] += a3 * bA.z; acc1[3][3] += a3 * bA.w;
            acc1[3][4] += a3 * bB.x; acc1[3][5] += a3 * bB.y; acc1[3][6] += a3 * bB.z; acc1[3][7] += a3 * bB.w;
        }
        __syncthreads();
    }

    // ---------------- bias + SiLU -> Hs ----------------
#pragma unroll
    for (int i = 0; i < 4; i++) {
        int row = rg * 4 + i;
#pragma unroll
        for (int j = 0; j < 8; j++) {
            float x = acc1[i][j] + b1[lane * 8 + j];
            Hs[row * HS_STRIDE + lane * 8 + j] = silu_f(x);
        }
    }
    __syncthreads();

    // ---------------- GEMM2: C2[32,D] = Hs[32,H] @ w2[H,D] ----------------
    float acc2[4][4];
#pragma unroll
    for (int i = 0; i < 4; i++)
#pragma unroll
        for (int j = 0; j < 4; j++) acc2[i][j] = 0.0f;

    for (int kt = 0; kt < H / 32; ++kt) {
        // Load w2 tile [32][128]: 4 float4 per thread (reuse Bs region)
#pragma unroll
        for (int j = 0; j < 4; j++) {
            int idx = tid + j * 256;
            int k  = idx >> 5;
            int n4 = idx & 31;
            ((float4*)Bs)[k * 32 + n4] =
                ((const float4*)(w2 + (size_t)(kt * 32 + k) * D))[n4];
        }
        __syncthreads();

#pragma unroll
        for (int kk = 0; kk < 32; ++kk) {
            float a0 = Hs[(rg * 4 + 0) * HS_STRIDE + kt * 32 + kk];
            float a1 = Hs[(rg * 4 + 1) * HS_STRIDE + kt * 32 + kk];
            float a2 = Hs[(rg * 4 + 2) * HS_STRIDE + kt * 32 + kk];
            float a3 = Hs[(rg * 4 + 3) * HS_STRIDE + kt * 32 + kk];
            float4 b = Bs4[kk * 32 + lane];
            acc2[0][0] += a0 * b.x; acc2[0][1] += a0 * b.y; acc2[0][2] += a0 * b.z; acc2[0][3] += a0 * b.w;
            acc2[1][0] += a1 * b.x; acc2[1][1] += a1 * b.y; acc2[1][2] += a1 * b.z; acc2[1][3] += a1 * b.w;
            acc2[2][0] += a2 * b.x; acc2[2][1] += a2 * b.y; acc2[2][2] += a2 * b.z; acc2[2][3] += a2 * b.w;
            acc2[3][0] += a3 * b.x; acc2[3][1] += a3 * b.y; acc2[3][2] += a3 * b.z; acc2[3][3] += a3 * b.w;
        }
        __syncthreads();
    }

    // ---------------- LayerNorm + residual + (edge) scatter ----------------
    // NOTE: grow = GLOBAL row (row0 + local). R5 bug: used local row here.
    const int c = lane * 4;
#pragma unroll
    for (int i = 0; i < 4; i++) {
        int grow = row0 + rg * 4 + i;       // global row (uniform per warp)
        if (grow >= M) continue;

        float v0 = acc2[i][0] + b2[c + 0];
        float v1 = acc2[i][1] + b2[c + 1];
        float v2 = acc2[i][2] + b2[c + 2];
        float v3 = acc2[i][3] + b2[c + 3];

        float s  = v0 + v1 + v2 + v3;
        float sq = v0 * v0 + v1 * v1 + v2 * v2 + v3 * v3;
#pragma unroll
        for (int o = 16; o > 0; o >>= 1) {
            s  += __shfl_xor_sync(0xffffffffu, s,  o);
            sq += __shfl_xor_sync(0xffffffffu, sq, o);
        }
        float mean = s * (1.0f / 128.0f);
        float var  = sq * (1.0f / 128.0f) - mean * mean;
        float rs   = rsqrtf(var + LN_EPS);

        float y0 = (v0 - mean) * rs * gm[c + 0] + bt[c + 0];
        float y1 = (v1 - mean) * rs * gm[c + 1] + bt[c + 1];
        float y2 = (v2 - mean) * rs * gm[c + 2] + bt[c + 2];
        float y3 = (v3 - mean) * rs * gm[c + 3] + bt[c + 3];

        if (MODE == 0) {
            float4 r4 = *(const float4*)(ea + (size_t)grow * D + c);
            float4 o4 = make_float4(r4.x + y0, r4.y + y1, r4.z + y2, r4.w + y3);
            *(float4*)(out + (size_t)grow * D + c) = o4;
            long long dn = is64 ? e64[E + grow] : (long long)e32[E + grow];
            size_t dbase = (size_t)dn * D + c;
            atomicAdd(&g_agg[dbase + 0], y0);
            atomicAdd(&g_agg[dbase + 1], y1);
            atomicAdd(&g_agg[dbase + 2], y2);
            atomicAdd(&g_agg[dbase + 3], y3);
            if (lane == 0) atomicAdd(&g_cnt[dn], 1.0f);
        } else if (MODE == 1) {
            float4 r4 = *(const float4*)(rx + (size_t)grow * D + c);
            float4 o4 = make_float4(r4.x + y0, r4.y + y1, r4.z + y2, r4.w + y3);
            *(float4*)(out + (size_t)grow * D + c) = o4;
        } else {
            float4 r4 = *(const float4*)(sx + (size_t)grow * D + c);
            float4 o4 = make_float4(r4.x + y0, r4.y + y1, r4.z + y2, r4.w + y3);
            *(float4*)(out + (size_t)grow * D + c) = o4;
        }
    }
}

extern "C" void kernel_launch(void* const* d_in, const int* in_sizes, int n_in,
                              void* d_out, int out_size)
{
    const float*     sx   = (const float*)d_in[0];
    const float*     rx   = (const float*)d_in[1];
    const float*     ea   = (const float*)d_in[2];
    const int*       e32  = (const int*)d_in[3];
    const long long* e64  = (const long long*)d_in[3];
    const float *ew1 = (const float*)d_in[4],  *eb1 = (const float*)d_in[5];
    const float *ew2 = (const float*)d_in[6],  *eb2 = (const float*)d_in[7];
    const float *eg  = (const float*)d_in[8],  *ebt = (const float*)d_in[9];
    const float *nw1 = (const float*)d_in[10], *nb1 = (const float*)d_in[11];
    const float *nw2 = (const float*)d_in[12], *nb2 = (const float*)d_in[13];
    const float *ng  = (const float*)d_in[14], *nbt = (const float*)d_in[15];
    const float *sw1 = (const float*)d_in[16], *sb1 = (const float*)d_in[17];
    const float *sw2 = (const float*)d_in[18], *sb2 = (const float*)d_in[19];
    const float *sg  = (const float*)d_in[20], *sbt = (const float*)d_in[21];

    const int N = in_sizes[0] / D;
    const int E = in_sizes[3] / 2;

    float* out          = (float*)d_out;
    float* sender_out   = out;
    float* receiver_out = out + (size_t)N * D;
    float* edge_out     = out + (size_t)2 * N * D;

    const size_t smem_bytes = (size_t)SMEM_FLOATS * sizeof(float);
    cudaFuncSetAttribute(mlp_kernel<3 * D, 0>, cudaFuncAttributeMaxDynamicSharedMemorySize, (int)smem_bytes);
    cudaFuncSetAttribute(mlp_kernel<2 * D, 1>, cudaFuncAttributeMaxDynamicSharedMemorySize, (int)smem_bytes);
    cudaFuncSetAttribute(mlp_kernel<D, 2>,     cudaFuncAttributeMaxDynamicSharedMemorySize, (int)smem_bytes);

    // 0) detect index dtype (int32 vs int64) into g_idx64
    probe_kernel<<<1, 32>>>(e32);

    // 1) zero scatter buffers (re-zeroed on every graph replay)
    zero_kernel<<<(N * (D + 1) + 255) / 256, 256>>>(N);

    // 2) edge MLP + residual + scatter
    mlp_kernel<3 * D, 0><<<(E + 31) / 32, 256, smem_bytes>>>(
        sx, rx, ea, e32, e64, ew1, eb1, ew2, eb2, eg, ebt, edge_out, E, E);

    // 3) node MLP + residual (consumes g_agg / g_cnt)
    mlp_kernel<2 * D, 1><<<(N + 31) / 32, 256, smem_bytes>>>(
        sx, rx, ea, e32, e64, nw1, nb1, nw2, nb2, ng, nbt, receiver_out, N, E);

    // 4) sender MLP + residual
    mlp_kernel<D, 2><<<(N + 31) / 32, 256, smem_bytes>>>(
        sx, rx, ea, e32, e64, sw1, sb1, sw2, sb2, sg, sbt, sender_out, N, E);
}

// round 8
// speedup vs baseline: 1.3086x; 1.3086x over previous
#include <cuda_runtime.h>
#include <cuda_bf16.h>
#include <cstdint>

// Problem constants (fixed-shape dataset)
#define D 128
#define H 256
#define MAXN 40000
#define LN_EPS 1e-5f

// Scratch: edge-message aggregation + per-receiver counts.
__device__ float g_agg[MAXN * D];
__device__ float g_cnt[MAXN];
__device__ int g_idx64;

// Pre-split, transposed weights: bf16 hi/lo planes, layout [n][k], k contiguous.
#define OFF_W1E 0
#define OFF_W1N 98304
#define OFF_W1S 163840
#define OFF_W2E 196608
#define OFF_W2N 229376
#define OFF_W2S 262144
#define WTOT    294912
__device__ __nv_bfloat16 g_whi[WTOT];
__device__ __nv_bfloat16 g_wlo[WTOT];

__device__ __forceinline__ float silu_f(float x) {
    return x / (1.0f + __expf(-x));
}

// Transpose + bf16 hi/lo split of one weight matrix src[K][N] -> planes [n][k].
__global__ void prep_kernel(const float* __restrict__ src, int dstoff, int K, int N) {
    int d = blockIdx.x * blockDim.x + threadIdx.x;
    if (d >= K * N) return;
    int n = d / K, k = d - n * K;
    float x = src[(size_t)k * N + n];
    __nv_bfloat16 h = __float2bfloat16(x);
    float r = x - __bfloat162float(h);
    g_whi[dstoff + d] = h;
    g_wlo[dstoff + d] = __float2bfloat16(r);
}

// Detect index dtype: int64 values < 2^31 have zero odd words.
__global__ void probe_kernel(const int* __restrict__ e32) {
    if (blockIdx.x == 0 && threadIdx.x == 0) {
        int all0 = 1;
#pragma unroll 1
        for (int i = 0; i < 64; ++i) {
            if (e32[2 * i + 1] != 0) { all0 = 0; break; }
        }
        g_idx64 = all0;
    }
}

__global__ void zero_kernel(int N) {
    int i = blockIdx.x * blockDim.x + threadIdx.x;
    int na = N * D;
    if (i < na) g_agg[i] = 0.0f;
    if (i < N)  g_cnt[i] = 0.0f;
}

// ---------------- mma helpers ----------------
__device__ __forceinline__ uint32_t pack_bf16x2(float lo, float hi) {
    uint32_t r;
    asm("cvt.rn.bf16x2.f32 %0, %1, %2;" : "=r"(r) : "f"(hi), "f"(lo));
    return r;
}
// Split two fp32 into bf16 hi-pair and lo-pair (residual).
__device__ __forceinline__ void split2(float2 f, uint32_t& h, uint32_t& l) {
    h = pack_bf16x2(f.x, f.y);
    float hx = __uint_as_float(h << 16);
    float hy = __uint_as_float(h & 0xffff0000u);
    l = pack_bf16x2(f.x - hx, f.y - hy);
}
__device__ __forceinline__ void mma_bf16(float c[4],
                                         uint32_t a0, uint32_t a1, uint32_t a2, uint32_t a3,
                                         uint32_t b0, uint32_t b1) {
    asm volatile(
        "mma.sync.aligned.m16n8k16.row.col.f32.bf16.bf16.f32 "
        "{%0,%1,%2,%3},{%4,%5,%6,%7},{%8,%9},{%0,%1,%2,%3};"
        : "+f"(c[0]), "+f"(c[1]), "+f"(c[2]), "+f"(c[3])
        : "r"(a0), "r"(a1), "r"(a2), "r"(a3), "r"(b0), "r"(b1));
}

// ---------------- smem layout (floats) ----------------
#define AS_STRIDE 44               // fp32 A tile stride (distinct banks for 8 rows, 16B aligned)
#define AS_BASE   0                // 32 x 44 = 1408
#define B1_BASE   1408             // 256 bias1
#define B2_BASE   1664             // 128 bias2
#define BS_BASE   1792             // bf16 planes: 2 x 10240 elems = 10240 floats
#define BS_STRIDE 40               // bf16 elems per n-row (80B; conflict-free fragment loads)
#define BS_PLANE  10240            // 256 * 40 elems
#define HS_BASE   12032            // 32 x 266 = 8512
#define HS_STRIDE 266
#define CS_STRIDE 132              // epilogue staging (reuses BS region)
#define SMEM_FLOATS 20544          // 82176 bytes

// Fused MLP+LN kernel, tensor-core (bf16 3-product split) version.
// MODE 0: edge (KTOT=384), MODE 1: node (256), MODE 2: sender (128).
// Block: 256 threads / 8 warps, 32 rows.
// GEMM1 warp tile: 16 rows x 64 cols (warp grid 2x4). GEMM2: 16 x 32 (2x4).
template <int KTOT, int MODE>
__global__ void __launch_bounds__(256, 2) mlp_kernel(
    const float* __restrict__ sx,
    const float* __restrict__ rx,
    const float* __restrict__ ea,
    const int* e32, const long long* e64,
    const float* __restrict__ b1, const float* __restrict__ b2,
    const float* __restrict__ gm, const float* __restrict__ bt,
    int w1off, int w2off,
    float* __restrict__ out,
    int M, int E)
{
    extern __shared__ float smem[];
    float* As = smem + AS_BASE;
    float* b1s = smem + B1_BASE;
    float* b2s = smem + B2_BASE;
    __nv_bfloat16* Bsh = (__nv_bfloat16*)(smem + BS_BASE);
    __nv_bfloat16* Bsl = Bsh + BS_PLANE;
    float* Hs = smem + HS_BASE;

    const int tid  = threadIdx.x;
    const int lane = tid & 31;
    const int warp = tid >> 5;
    const int row0 = blockIdx.x * 32;
    const int is64 = (MODE == 0) ? g_idx64 : 0;

    const int r0  = (warp & 1) * 16;       // warp row base (both GEMMs)
    const int n0  = (warp >> 1) * 64;      // GEMM1 col base
    const int m0  = (warp >> 1) * 32;      // GEMM2 col base
    const int g   = lane >> 2;             // group id
    const int tig = lane & 3;              // thread in group

    // stage biases
    b1s[tid] = b1[tid & 255] ;             // tid<256 always; H=256
    if (tid < 128) b2s[tid] = b2[tid];

    // ================= GEMM1: C1[32,256] = A[32,KTOT] @ W1 =================
    float c1[8][4];
#pragma unroll
    for (int j = 0; j < 8; j++)
#pragma unroll
        for (int q = 0; q < 4; q++) c1[j][q] = 0.0f;

    for (int kt = 0; kt < KTOT / 32; ++kt) {
        // ---- stage A tile fp32 [32][32] (gather) ----
        {
            int r  = tid >> 3;
            int kl = (tid & 7) * 4;
            int kg = kt * 32 + kl;
            int row = row0 + r;
            float4 v = make_float4(0.f, 0.f, 0.f, 0.f);
            if (row < M) {
                if (MODE == 0) {
                    const float* p;
                    if (kg < 128) {
                        long long s = is64 ? e64[row] : (long long)e32[row];
                        p = sx + (size_t)s * D + kg;
                    } else if (kg < 256) {
                        long long dd = is64 ? e64[E + row] : (long long)e32[E + row];
                        p = rx + (size_t)dd * D + (kg - 128);
                    } else {
                        p = ea + (size_t)row * D + (kg - 256);
                    }
                    v = *(const float4*)p;
                } else if (MODE == 1) {
                    if (kg < 128) {
                        v = *(const float4*)(rx + (size_t)row * D + kg);
                    } else {
                        float rc = 1.0f / fmaxf(g_cnt[row], 1.0f);
                        float4 t = *(const float4*)(g_agg + (size_t)row * D + (kg - 128));
                        v.x = t.x * rc; v.y = t.y * rc; v.z = t.z * rc; v.w = t.w * rc;
                    }
                } else {
                    v = *(const float4*)(sx + (size_t)row * D + kg);
                }
            }
            *(float4*)(As + r * AS_STRIDE + kl) = v;
        }
        // ---- stage W1 tile (pre-split bf16): all 256 n, 32 k ----
        {
            int n = tid;
            const uint4* sh = (const uint4*)(g_whi + w1off + (size_t)n * KTOT + kt * 32);
            const uint4* sl = (const uint4*)(g_wlo + w1off + (size_t)n * KTOT + kt * 32);
            uint4* dh = (uint4*)(Bsh + n * BS_STRIDE);
            uint4* dl = (uint4*)(Bsl + n * BS_STRIDE);
#pragma unroll
            for (int j = 0; j < 4; j++) { dh[j] = sh[j]; dl[j] = sl[j]; }
        }
        __syncthreads();

#pragma unroll
        for (int kc = 0; kc < 2; ++kc) {
            const int kb = kc * 16;
            uint32_t ah[4], al[4];
            split2(*(const float2*)(As + (r0 + g)     * AS_STRIDE + kb + tig * 2),     ah[0], al[0]);
            split2(*(const float2*)(As + (r0 + g + 8) * AS_STRIDE + kb + tig * 2),     ah[1], al[1]);
            split2(*(const float2*)(As + (r0 + g)     * AS_STRIDE + kb + tig * 2 + 8), ah[2], al[2]);
            split2(*(const float2*)(As + (r0 + g + 8) * AS_STRIDE + kb + tig * 2 + 8), ah[3], al[3]);
#pragma unroll
            for (int j = 0; j < 8; j++) {
                int nn = n0 + 8 * j + g;
                uint32_t bh0 = *(const uint32_t*)(Bsh + nn * BS_STRIDE + kb + tig * 2);
                uint32_t bh1 = *(const uint32_t*)(Bsh + nn * BS_STRIDE + kb + tig * 2 + 8);
                uint32_t bl0 = *(const uint32_t*)(Bsl + nn * BS_STRIDE + kb + tig * 2);
                uint32_t bl1 = *(const uint32_t*)(Bsl + nn * BS_STRIDE + kb + tig * 2 + 8);
                mma_bf16(c1[j], ah[0], ah[1], ah[2], ah[3], bh0, bh1);
                mma_bf16(c1[j], ah[0], ah[1], ah[2], ah[3], bl0, bl1);
                mma_bf16(c1[j], al[0], al[1], al[2], al[3], bh0, bh1);
            }
        }
        __syncthreads();
    }

    // ---- bias + SiLU -> Hs (fp32) ----
#pragma unroll
    for (int j = 0; j < 8; j++) {
        int col = n0 + 8 * j + tig * 2;
        float2 p0 = make_float2(silu_f(c1[j][0] + b1s[col]), silu_f(c1[j][1] + b1s[col + 1]));
        float2 p1 = make_float2(silu_f(c1[j][2] + b1s[col]), silu_f(c1[j][3] + b1s[col + 1]));
        *(float2*)(Hs + (r0 + g)     * HS_STRIDE + col) = p0;
        *(float2*)(Hs + (r0 + g + 8) * HS_STRIDE + col) = p1;
    }

    // ================= GEMM2: C2[32,128] = Hs[32,256] @ W2 =================
    float c2[4][4];
#pragma unroll
    for (int j = 0; j < 4; j++)
#pragma unroll
        for (int q = 0; q < 4; q++) c2[j][q] = 0.0f;

    for (int kt = 0; kt < H / 32; ++kt) {
        // stage W2 tile: 128 n, 32 k; 2 threads per n
        {
            int n = tid >> 1, half = tid & 1;
            const uint4* sh = (const uint4*)(g_whi + w2off + (size_t)n * H + kt * 32 + half * 16);
            const uint4* sl = (const uint4*)(g_wlo + w2off + (size_t)n * H + kt * 32 + half * 16);
            uint4* dh = (uint4*)(Bsh + n * BS_STRIDE + half * 16);
            uint4* dl = (uint4*)(Bsl + n * BS_STRIDE + half * 16);
            dh[0] = sh[0]; dh[1] = sh[1];
            dl[0] = sl[0]; dl[1] = sl[1];
        }
        __syncthreads();   // also orders Hs writes (all warps) before reads

#pragma unroll
        for (int kc = 0; kc < 2; ++kc) {
            const int kb  = kt * 32 + kc * 16;   // Hs k index
            const int kbl = kc * 16;             // Bs k index
            uint32_t ah[4], al[4];
            split2(*(const float2*)(Hs + (r0 + g)     * HS_STRIDE + kb + tig * 2),     ah[0], al[0]);
            split2(*(const float2*)(Hs + (r0 + g + 8) * HS_STRIDE + kb + tig * 2),     ah[1], al[1]);
            split2(*(const float2*)(Hs + (r0 + g)     * HS_STRIDE + kb + tig * 2 + 8), ah[2], al[2]);
            split2(*(const float2*)(Hs + (r0 + g + 8) * HS_STRIDE + kb + tig * 2 + 8), ah[3], al[3]);
#pragma unroll
            for (int j = 0; j < 4; j++) {
                int nn = m0 + 8 * j + g;
                uint32_t bh0 = *(const uint32_t*)(Bsh + nn * BS_STRIDE + kbl + tig * 2);
                uint32_t bh1 = *(const uint32_t*)(Bsh + nn * BS_STRIDE + kbl + tig * 2 + 8);
                uint32_t bl0 = *(const uint32_t*)(Bsl + nn * BS_STRIDE + kbl + tig * 2);
                uint32_t bl1 = *(const uint32_t*)(Bsl + nn * BS_STRIDE + kbl + tig * 2 + 8);
                mma_bf16(c2[j], ah[0], ah[1], ah[2], ah[3], bh0, bh1);
                mma_bf16(c2[j], ah[0], ah[1], ah[2], ah[3], bl0, bl1);
                mma_bf16(c2[j], al[0], al[1], al[2], al[3], bh0, bh1);
            }
        }
        __syncthreads();
    }

    // ---- stage C2 to smem (reuse Bs region), then LN epilogue ----
    float* Cs = smem + BS_BASE;
#pragma unroll
    for (int j = 0; j < 4; j++) {
        int col = m0 + 8 * j + tig * 2;
        *(float2*)(Cs + (r0 + g)     * CS_STRIDE + col) = make_float2(c2[j][0], c2[j][1]);
        *(float2*)(Cs + (r0 + g + 8) * CS_STRIDE + col) = make_float2(c2[j][2], c2[j][3]);
    }
    __syncthreads();

    // LayerNorm + residual + (edge) scatter — thread (rg,lane): rows rg*4..+3, cols lane*4..+3
    const int rg = warp;
    const int c  = lane * 4;
#pragma unroll
    for (int i = 0; i < 4; i++) {
        int grow = row0 + rg * 4 + i;   // global row (uniform per warp)
        if (grow >= M) continue;

        float4 vv = *(const float4*)(Cs + (rg * 4 + i) * CS_STRIDE + c);
        float v0 = vv.x + b2s[c + 0];
        float v1 = vv.y + b2s[c + 1];
        float v2 = vv.z + b2s[c + 2];
        float v3 = vv.w + b2s[c + 3];

        float s  = v0 + v1 + v2 + v3;
        float sq = v0 * v0 + v1 * v1 + v2 * v2 + v3 * v3;
#pragma unroll
        for (int o = 16; o > 0; o >>= 1) {
            s  += __shfl_xor_sync(0xffffffffu, s,  o);
            sq += __shfl_xor_sync(0xffffffffu, sq, o);
        }
        float mean = s * (1.0f / 128.0f);
        float var  = sq * (1.0f / 128.0f) - mean * mean;
        float rs   = rsqrtf(var + LN_EPS);

        float y0 = (v0 - mean) * rs * gm[c + 0] + bt[c + 0];
        float y1 = (v1 - mean) * rs * gm[c + 1] + bt[c + 1];
        float y2 = (v2 - mean) * rs * gm[c + 2] + bt[c + 2];
        float y3 = (v3 - mean) * rs * gm[c + 3] + bt[c + 3];

        if (MODE == 0) {
            float4 r4 = *(const float4*)(ea + (size_t)grow * D + c);
            *(float4*)(out + (size_t)grow * D + c) =
                make_float4(r4.x + y0, r4.y + y1, r4.z + y2, r4.w + y3);
            long long dn = is64 ? e64[E + grow] : (long long)e32[E + grow];
            size_t dbase = (size_t)dn * D + c;
            atomicAdd(&g_agg[dbase + 0], y0);
            atomicAdd(&g_agg[dbase + 1], y1);
            atomicAdd(&g_agg[dbase + 2], y2);
            atomicAdd(&g_agg[dbase + 3], y3);
            if (lane == 0) atomicAdd(&g_cnt[dn], 1.0f);
        } else if (MODE == 1) {
            float4 r4 = *(const float4*)(rx + (size_t)grow * D + c);
            *(float4*)(out + (size_t)grow * D + c) =
                make_float4(r4.x + y0, r4.y + y1, r4.z + y2, r4.w + y3);
        } else {
            float4 r4 = *(const float4*)(sx + (size_t)grow * D + c);
            *(float4*)(out + (size_t)grow * D + c) =
                make_float4(r4.x + y0, r4.y + y1, r4.z + y2, r4.w + y3);
        }
    }
}

extern "C" void kernel_launch(void* const* d_in, const int* in_sizes, int n_in,
                              void* d_out, int out_size)
{
    const float*     sx   = (const float*)d_in[0];
    const float*     rx   = (const float*)d_in[1];
    const float*     ea   = (const float*)d_in[2];
    const int*       e32  = (const int*)d_in[3];
    const long long* e64  = (const long long*)d_in[3];
    const float *ew1 = (const float*)d_in[4],  *eb1 = (const float*)d_in[5];
    const float *ew2 = (const float*)d_in[6],  *eb2 = (const float*)d_in[7];
    const float *eg  = (const float*)d_in[8],  *ebt = (const float*)d_in[9];
    const float *nw1 = (const float*)d_in[10], *nb1 = (const float*)d_in[11];
    const float *nw2 = (const float*)d_in[12], *nb2 = (const float*)d_in[13];
    const float *ng  = (const float*)d_in[14], *nbt = (const float*)d_in[15];
    const float *sw1 = (const float*)d_in[16], *sb1 = (const float*)d_in[17];
    const float *sw2 = (const float*)d_in[18], *sb2 = (const float*)d_in[19];
    const float *sg  = (const float*)d_in[20], *sbt = (const float*)d_in[21];

    const int N = in_sizes[0] / D;
    const int E = in_sizes[3] / 2;

    float* out          = (float*)d_out;
    float* sender_out   = out;
    float* receiver_out = out + (size_t)N * D;
    float* edge_out     = out + (size_t)2 * N * D;

    const size_t smem_bytes = (size_t)SMEM_FLOATS * sizeof(float);
    cudaFuncSetAttribute(mlp_kernel<3 * D, 0>, cudaFuncAttributeMaxDynamicSharedMemorySize, (int)smem_bytes);
    cudaFuncSetAttribute(mlp_kernel<2 * D, 1>, cudaFuncAttributeMaxDynamicSharedMemorySize, (int)smem_bytes);
    cudaFuncSetAttribute(mlp_kernel<D, 2>,     cudaFuncAttributeMaxDynamicSharedMemorySize, (int)smem_bytes);

    // 0) weight prep: transpose + bf16 hi/lo split (6 tiny launches)
    prep_kernel<<<(384 * 256 + 255) / 256, 256>>>(ew1, OFF_W1E, 384, 256);
    prep_kernel<<<(256 * 256 + 255) / 256, 256>>>(nw1, OFF_W1N, 256, 256);
    prep_kernel<<<(128 * 256 + 255) / 256, 256>>>(sw1, OFF_W1S, 128, 256);
    prep_kernel<<<(256 * 128 + 255) / 256, 256>>>(ew2, OFF_W2E, 256, 128);
    prep_kernel<<<(256 * 128 + 255) / 256, 256>>>(nw2, OFF_W2N, 256, 128);
    prep_kernel<<<(256 * 128 + 255) / 256, 256>>>(sw2, OFF_W2S, 256, 128);

    // 1) index dtype probe + scatter buffer zeroing
    probe_kernel<<<1, 32>>>(e32);
    zero_kernel<<<(N * (D + 1) + 255) / 256, 256>>>(N);

    // 2) edge MLP + residual + scatter
    mlp_kernel<3 * D, 0><<<(E + 31) / 32, 256, smem_bytes>>>(
        sx, rx, ea, e32, e64, eb1, eb2, eg, ebt, OFF_W1E, OFF_W2E, edge_out, E, E);

    // 3) node MLP + residual (consumes g_agg / g_cnt)
    mlp_kernel<2 * D, 1><<<(N + 31) / 32, 256, smem_bytes>>>(
        sx, rx, ea, e32, e64, nb1, nb2, ng, nbt, OFF_W1N, OFF_W2N, receiver_out, N, E);

    // 4) sender MLP + residual
    mlp_kernel<D, 2><<<(N + 31) / 32, 256, smem_bytes>>>(
        sx, rx, ea, e32, e64, sb1, sb2, sg, sbt, OFF_W1S, OFF_W2S, sender_out, N, E);
}